// round 4
// baseline (speedup 1.0000x reference)
#include <cuda_runtime.h>

#define NQ      10
#define DIM     1024
#define TSTEPS  10
#define NDATA   1024
#define NGATES  (TSTEPS * NQ)

typedef unsigned long long u64;

// ---- packed f32x2 helpers (FFMA2 only reachable via PTX) ----
__device__ __forceinline__ u64 pk(float x, float y) {
    u64 u; asm("mov.b64 %0, {%1,%2};" : "=l"(u) : "f"(x), "f"(y)); return u;
}
__device__ __forceinline__ void upk(u64 u, float &x, float &y) {
    asm("mov.b64 {%0,%1}, %2;" : "=f"(x), "=f"(y) : "l"(u));
}
__device__ __forceinline__ u64 swp(u64 u) { float x, y; upk(u, x, y); return pk(y, x); }
__device__ __forceinline__ u64 ffma2(u64 a, u64 b, u64 c) {
    u64 d; asm("fma.rn.f32x2 %0, %1, %2, %3;" : "=l"(d) : "l"(a), "l"(b), "l"(c)); return d;
}
__device__ __forceinline__ u64 fmul2(u64 a, u64 b) {
    u64 d; asm("mul.rn.f32x2 %0, %1, %2;" : "=l"(d) : "l"(a), "l"(b)); return d;
}
__device__ __forceinline__ void ldc(float4 v, u64 &A, u64 &B) {
    A = pk(v.x, v.y); B = pk(v.z, v.w);
}

// XOR swizzle for the state-transpose buffer: conflict-free in both directions
#define SWZ(j) (((j) & ~31) | (((j) ^ ((j) >> 5)) & 31))

__global__ __launch_bounds__(32)
void scramble_kernel(const float* __restrict__ in_re,
                     const float* __restrict__ in_im,
                     const float* __restrict__ phis,
                     const float* __restrict__ gs,
                     float* __restrict__ out)
{
    __shared__ float4 s_gm[NGATES][4];          // (mx,mx,-my,my) per matrix element
    __shared__ float4 s_ph[TSTEPS * (NQ + 1)];  // (c,c,-s,s) by popcount
    __shared__ u64    s_x[DIM];                 // transpose buffer

    const int lane = threadIdx.x;
    const int b    = blockIdx.x;

    // ---- precompute 100 gate matrices ----
    for (int g = lane; g < NGATES; g += 32) {
        int tt = g / NQ, i = g - tt * NQ;
        int base = b * (3 * NQ * TSTEPS) + 3 * NQ * tt;
        float a  = phis[base + i];
        float th = phis[base + NQ + i];
        float bb = phis[base + 2 * NQ + i];
        float c, s, ca, sa, cd, sd;
        __sincosf(0.5f * th,       &s,  &c);
        __sincosf(0.5f * (a + bb), &sa, &ca);
        __sincosf(0.5f * (a - bb), &sd, &cd);
        // m00=(c ca,-c sa) m01=(-s cd,-s sd) m10=(s cd,-s sd) m11=(c ca,c sa)
        s_gm[g][0] = make_float4( c * ca,  c * ca,  c * sa, -c * sa);
        s_gm[g][1] = make_float4(-s * cd, -s * cd,  s * sd, -s * sd);
        s_gm[g][2] = make_float4( s * cd,  s * cd,  s * sd, -s * sd);
        s_gm[g][3] = make_float4( c * ca,  c * ca, -c * sa,  c * sa);
    }
    // ---- diagonal phase tables ----
    for (int u = lane; u < TSTEPS * (NQ + 1); u += 32) {
        int tt = u / (NQ + 1), k = u - tt * (NQ + 1);
        const float inv = 0.15811388300841897f;   // 1/(2*sqrt(10))
        float theta = gs[b * TSTEPS + tt] * inv;
        float zs = 10.f - 2.f * (float)k;
        float ps = 0.5f * (zs * zs - 10.f);
        float sn, cs;
        __sincosf(-0.5f * theta * ps, &sn, &cs);
        s_ph[u] = make_float4(cs, cs, -sn, sn);
    }

    // ---- load state, layout A: psi[r] holds j = (r<<5)|lane ----
    u64 psi[32];
    float nrm = 0.f;
    #pragma unroll
    for (int r = 0; r < 32; r++) {
        int j = (r << 5) | lane;
        float re = in_re[b * DIM + j];
        float im = in_im[b * DIM + j];
        psi[r] = pk(re, im);
        nrm += re * re + im * im;
    }
    #pragma unroll
    for (int off = 16; off; off >>= 1)
        nrm += __shfl_xor_sync(0xFFFFFFFFu, nrm, off);
    const float invn = rsqrtf(nrm);
    const int pl = __popc(lane);
    __syncwarp();

    // ---- 20 half-steps: gates(5) / transpose / gates(5) / phase, layouts alternate ----
    #pragma unroll 1
    for (int h = 0; h < 2 * TSTEPS; h++) {
        const int tt  = h >> 1;
        const int off = (((h + 1) >> 1) & 1) ? 5 : 0;   // 0,5,5,0,0,5,5,0,...

        // 5 register-local butterflies (masks identical in both layouts)
        #pragma unroll
        for (int k = 0; k < 5; k++) {
            const int m = 16 >> k;
            const float4* gg = s_gm[tt * NQ + off + k];
            u64 c00A, c00B, c01A, c01B, c10A, c10B, c11A, c11B;
            ldc(gg[0], c00A, c00B); ldc(gg[1], c01A, c01B);
            ldc(gg[2], c10A, c10B); ldc(gg[3], c11A, c11B);
            #pragma unroll
            for (int rr = 0; rr < 16; rr++) {
                int r0 = ((rr & ~(m - 1)) << 1) | (rr & (m - 1));
                int r1 = r0 | m;
                u64 p0 = psi[r0], p1 = psi[r1];
                u64 p0s = swp(p0), p1s = swp(p1);
                psi[r0] = ffma2(c01B, p1s, ffma2(c01A, p1,
                          ffma2(c00B, p0s, fmul2(c00A, p0))));
                psi[r1] = ffma2(c11B, p1s, ffma2(c11A, p1,
                          ffma2(c10B, p0s, fmul2(c10A, p0))));
            }
        }

        if ((h & 1) == 0) {
            // transpose: A->B on h=0,4,8,..., B->A on h=2,6,10,...
            const bool toB = ((h >> 1) & 1) == 0;
            __syncwarp();
            #pragma unroll
            for (int r = 0; r < 32; r++) {
                int j = toB ? ((r << 5) | lane) : ((lane << 5) | r);
                s_x[SWZ(j)] = psi[r];
            }
            __syncwarp();
            #pragma unroll
            for (int r = 0; r < 32; r++) {
                int j = toB ? ((lane << 5) | r) : ((r << 5) | lane);
                psi[r] = s_x[SWZ(j)];
            }
        } else {
            // diagonal entangling phase (popcount is layout-independent)
            #pragma unroll
            for (int r = 0; r < 32; r++) {
                float4 f4 = s_ph[tt * (NQ + 1) + pl + __popc(r)];
                u64 fA, fB; ldc(f4, fA, fB);
                psi[r] = ffma2(fB, swp(psi[r]), fmul2(fA, psi[r]));
            }
        }
    }

    // ---- ends in layout A; store with deferred normalization ----
    #pragma unroll
    for (int r = 0; r < 32; r++) {
        int j = (r << 5) | lane;
        float x, y; upk(psi[r], x, y);
        out[b * DIM + j]               = x * invn;
        out[NDATA * DIM + b * DIM + j] = y * invn;
    }
}

extern "C" void kernel_launch(void* const* d_in, const int* in_sizes, int n_in,
                              void* d_out, int out_size)
{
    const float* in_re = (const float*)d_in[0];
    const float* in_im = (const float*)d_in[1];
    const float* phis  = (const float*)d_in[2];
    const float* gs    = (const float*)d_in[3];
    float* out = (float*)d_out;
    scramble_kernel<<<NDATA, 32>>>(in_re, in_im, phis, gs, out);
}

// round 5
// speedup vs baseline: 1.6683x; 1.6683x over previous
#include <cuda_runtime.h>

#define NQ      10
#define DIM     1024
#define TSTEPS  10
#define NDATA   1024
#define NGATES  (TSTEPS * NQ)
#define NTHREADS 128               // 4 warps = 1 sample, 8 amplitudes/thread
#define AMPS    8

typedef unsigned long long u64;

// ---- packed f32x2 helpers (FFMA2 only reachable via PTX) ----
__device__ __forceinline__ u64 pk(float x, float y) {
    u64 u; asm("mov.b64 %0, {%1,%2};" : "=l"(u) : "f"(x), "f"(y)); return u;
}
__device__ __forceinline__ void upk(u64 u, float &x, float &y) {
    asm("mov.b64 {%0,%1}, %2;" : "=f"(x), "=f"(y) : "l"(u));
}
__device__ __forceinline__ u64 swp(u64 u) { float x, y; upk(u, x, y); return pk(y, x); }
__device__ __forceinline__ u64 ffma2(u64 a, u64 b, u64 c) {
    u64 d; asm("fma.rn.f32x2 %0, %1, %2, %3;" : "=l"(d) : "l"(a), "l"(b), "l"(c)); return d;
}
__device__ __forceinline__ u64 fmul2(u64 a, u64 b) {
    u64 d; asm("mul.rn.f32x2 %0, %1, %2;" : "=l"(d) : "l"(a), "l"(b)); return d;
}
__device__ __forceinline__ void ldc(float4 v, u64 &A, u64 &B) {
    A = pk(v.x, v.y); B = pk(v.z, v.w);
}

__global__ __launch_bounds__(NTHREADS)
void scramble_kernel(const float* __restrict__ in_re,
                     const float* __restrict__ in_im,
                     const float* __restrict__ phis,
                     const float* __restrict__ gs,
                     float* __restrict__ out)
{
    __shared__ float4 s_gm[NGATES][4];          // (mx,mx,-my,my) per matrix element
    __shared__ float4 s_ph[TSTEPS * (NQ + 1)];  // (c,c,-s,s) by popcount
    __shared__ u64    s_x[DIM];                 // cross-warp exchange buffer
    __shared__ float  s_nrm[4];

    const int tid  = threadIdx.x;
    const int w    = tid >> 5;                  // 2 warp bits = qubits 0,1
    const int lane = tid & 31;                  // 5 lane bits = qubits 5..9
    const int b    = blockIdx.x;

    // ---- precompute 100 gate matrices (one per thread) ----
    if (tid < NGATES) {
        int g = tid;
        int tt = g / NQ, i = g - tt * NQ;
        int base = b * (3 * NQ * TSTEPS) + 3 * NQ * tt;
        float a  = phis[base + i];
        float th = phis[base + NQ + i];
        float bb = phis[base + 2 * NQ + i];
        float c, s, ca, sa, cd, sd;
        __sincosf(0.5f * th,       &s,  &c);
        __sincosf(0.5f * (a + bb), &sa, &ca);
        __sincosf(0.5f * (a - bb), &sd, &cd);
        // m00=(c ca,-c sa) m01=(-s cd,-s sd) m10=(s cd,-s sd) m11=(c ca,c sa)
        s_gm[g][0] = make_float4( c * ca,  c * ca,  c * sa, -c * sa);
        s_gm[g][1] = make_float4(-s * cd, -s * cd,  s * sd, -s * sd);
        s_gm[g][2] = make_float4( s * cd,  s * cd,  s * sd, -s * sd);
        s_gm[g][3] = make_float4( c * ca,  c * ca, -c * sa,  c * sa);
    } else if (tid < NGATES + TSTEPS * (NQ + 1) - NGATES + NGATES) { /* fallthrough below */ }
    // ---- diagonal phase tables (110 entries) ----
    {
        int u = tid - NGATES;                   // threads 100..127 do first 28
        for (; u < TSTEPS * (NQ + 1); u += NTHREADS - NGATES) {
            if (u < 0) break;
            int tt = u / (NQ + 1), k = u - tt * (NQ + 1);
            const float inv = 0.15811388300841897f;   // 1/(2*sqrt(10))
            float theta = gs[b * TSTEPS + tt] * inv;
            float zs = 10.f - 2.f * (float)k;
            float ps = 0.5f * (zs * zs - 10.f);
            float sn, cs;
            __sincosf(-0.5f * theta * ps, &sn, &cs);
            s_ph[u] = make_float4(cs, cs, -sn, sn);
        }
    }

    // ---- load 8 amplitudes: j = (w<<8)|(r<<5)|lane (lane contiguous -> coalesced) ----
    u64 psi[AMPS];
    float nrm = 0.f;
    #pragma unroll
    for (int r = 0; r < AMPS; r++) {
        int j = (w << 8) | (r << 5) | lane;
        float re = in_re[b * DIM + j];
        float im = in_im[b * DIM + j];
        psi[r] = pk(re, im);
        nrm += re * re + im * im;
    }
    #pragma unroll
    for (int off = 16; off; off >>= 1)
        nrm += __shfl_xor_sync(0xFFFFFFFFu, nrm, off);
    if (lane == 0) s_nrm[w] = nrm;
    __syncthreads();
    const float invn = rsqrtf(s_nrm[0] + s_nrm[1] + s_nrm[2] + s_nrm[3]);
    const int pb = __popc(lane) + __popc(w);

    for (int tt = 0; tt < TSTEPS; tt++) {
        // ---- qubits 0,1: warp-bit gates via smem exchange ----
        #pragma unroll
        for (int q = 0; q < 2; q++) {
            const int mw = 2 >> q;              // warp-bit mask
            const float4* gg = s_gm[tt * NQ + q];
            __syncthreads();
            #pragma unroll
            for (int r = 0; r < AMPS; r++)
                s_x[(w << 8) | (r << 5) | lane] = psi[r];
            __syncthreads();
            const bool hi = (w & mw) != 0;
            float4 own4 = hi ? gg[3] : gg[0];
            float4 oth4 = hi ? gg[2] : gg[1];
            u64 A, Ab, B, Bb;
            ldc(own4, A, Ab); ldc(oth4, B, Bb);
            const int pbase = ((w ^ mw) << 8) | lane;
            #pragma unroll
            for (int r = 0; r < AMPS; r++) {
                u64 oth = s_x[pbase | (r << 5)];
                psi[r] = ffma2(Bb, swp(oth),
                         ffma2(B,  oth,
                         ffma2(Ab, swp(psi[r]),
                         fmul2(A,  psi[r]))));
            }
        }
        // ---- qubits 2..4: register-local butterflies ----
        #pragma unroll
        for (int i = 2; i < 5; i++) {
            const int m = 1 << (4 - i);         // 4, 2, 1 in r-space
            const float4* gg = s_gm[tt * NQ + i];
            u64 c00A, c00B, c01A, c01B, c10A, c10B, c11A, c11B;
            ldc(gg[0], c00A, c00B); ldc(gg[1], c01A, c01B);
            ldc(gg[2], c10A, c10B); ldc(gg[3], c11A, c11B);
            #pragma unroll
            for (int rr = 0; rr < AMPS / 2; rr++) {
                int r0 = ((rr & ~(m - 1)) << 1) | (rr & (m - 1));
                int r1 = r0 | m;
                u64 p0 = psi[r0], p1 = psi[r1];
                u64 p0s = swp(p0), p1s = swp(p1);
                psi[r0] = ffma2(c01B, p1s, ffma2(c01A, p1,
                          ffma2(c00B, p0s, fmul2(c00A, p0))));
                psi[r1] = ffma2(c11B, p1s, ffma2(c11A, p1,
                          ffma2(c10B, p0s, fmul2(c10A, p0))));
            }
        }
        // ---- qubits 5..9: lane-bit gates via warp shuffle ----
        #pragma unroll
        for (int i = 5; i < 10; i++) {
            const int m = 1 << (9 - i);         // 16..1 in lane-space
            const float4* gg = s_gm[tt * NQ + i];
            const bool hi = (lane & m) != 0;
            float4 own4 = hi ? gg[3] : gg[0];
            float4 oth4 = hi ? gg[2] : gg[1];
            u64 A, Ab, B, Bb;
            ldc(own4, A, Ab); ldc(oth4, B, Bb);
            #pragma unroll
            for (int r = 0; r < AMPS; r++) {
                float x, y; upk(psi[r], x, y);
                float ox = __shfl_xor_sync(0xFFFFFFFFu, x, m);
                float oy = __shfl_xor_sync(0xFFFFFFFFu, y, m);
                psi[r] = ffma2(Bb, pk(oy, ox),
                         ffma2(B,  pk(ox, oy),
                         ffma2(Ab, pk(y, x),
                         fmul2(A,  psi[r]))));
            }
        }
        // ---- diagonal entangling phase ----
        #pragma unroll
        for (int r = 0; r < AMPS; r++) {
            float4 f4 = s_ph[tt * (NQ + 1) + pb + __popc(r)];
            u64 fA, fB; ldc(f4, fA, fB);
            psi[r] = ffma2(fB, swp(psi[r]), fmul2(fA, psi[r]));
        }
    }

    // ---- store with deferred normalization (coalesced) ----
    #pragma unroll
    for (int r = 0; r < AMPS; r++) {
        int j = (w << 8) | (r << 5) | lane;
        float x, y; upk(psi[r], x, y);
        out[b * DIM + j]               = x * invn;
        out[NDATA * DIM + b * DIM + j] = y * invn;
    }
}

extern "C" void kernel_launch(void* const* d_in, const int* in_sizes, int n_in,
                              void* d_out, int out_size)
{
    const float* in_re = (const float*)d_in[0];
    const float* in_im = (const float*)d_in[1];
    const float* phis  = (const float*)d_in[2];
    const float* gs    = (const float*)d_in[3];
    float* out = (float*)d_out;
    scramble_kernel<<<NDATA, NTHREADS>>>(in_re, in_im, phis, gs, out);
}

// round 6
// speedup vs baseline: 2.2587x; 1.3538x over previous
#include <cuda_runtime.h>

#define NQ      10
#define DIM     1024
#define TSTEPS  10
#define NDATA   1024
#define NTHREADS 128               // 4 warps = 1 sample
#define AMPS    8

typedef unsigned long long u64;

__device__ __forceinline__ u64 pk(float x, float y) {
    u64 u; asm("mov.b64 %0, {%1,%2};" : "=l"(u) : "f"(x), "f"(y)); return u;
}
__device__ __forceinline__ void upk(u64 u, float &x, float &y) {
    asm("mov.b64 {%0,%1}, %2;" : "=f"(x), "=f"(y) : "l"(u));
}
__device__ __forceinline__ u64 swp(u64 u) { float x, y; upk(u, x, y); return pk(y, x); }
__device__ __forceinline__ u64 ffma2(u64 a, u64 b, u64 c) {
    u64 d; asm("fma.rn.f32x2 %0, %1, %2, %3;" : "=l"(d) : "l"(a), "l"(b), "l"(c)); return d;
}
__device__ __forceinline__ u64 fmul2(u64 a, u64 b) {
    u64 d; asm("mul.rn.f32x2 %0, %1, %2;" : "=l"(d) : "l"(a), "l"(b)); return d;
}

__global__ __launch_bounds__(NTHREADS)
void scramble_kernel(const float* __restrict__ in_re,
                     const float* __restrict__ in_im,
                     const float* __restrict__ phis,
                     const float* __restrict__ gs,
                     float* __restrict__ out)
{
    // j = (w<<8)|(r<<5)|lane ; qubit i <-> j-bit (9-i)
    __shared__ u64    s_x[2][DIM];            // double-buffered exchange
    __shared__ float2 s_rot[TSTEPS * NQ];     // (cos(th/2), sin(th/2))
    __shared__ float  s_wgt[11][NQ];          // merged diag weights w_i(t)=a_i(t)+b_i(t-1)
    __shared__ float  s_lane[11 * 32];        // sum of weights over set lane bits
    __shared__ float  s_reg[11 * 8];          // over set r bits
    __shared__ float  s_w[11 * 4];            // over set w bits, + (-0.5*sum_all)
    __shared__ float  s_phi[11 * 11];         // entangling phase by popcount (shifted)
    __shared__ float  s_nrm[4];

    const int tid  = threadIdx.x;
    const int w    = tid >> 5;
    const int lane = tid & 31;
    const int b    = blockIdx.x;
    const float* P = phis + b * (3 * NQ * TSTEPS);

    // ---- rotation coefficients: c,s of th/2 ----
    if (tid < TSTEPS * NQ) {
        int tt = tid / NQ, i = tid - tt * NQ;
        float th = P[30 * tt + NQ + i];
        float s, c; __sincosf(0.5f * th, &s, &c);
        s_rot[tid] = make_float2(c, s);
    }
    // ---- merged diagonal weights: w_i(t) = a_i(t) + b_i(t-1), t=0..10 ----
    if (tid < 110) {
        int tt = tid / NQ, i = tid - tt * NQ;
        float v = 0.f;
        if (tt < 10) v += P[30 * tt + i];             // a_i(t)
        if (tt > 0)  v += P[30 * (tt - 1) + 2 * NQ + i]; // b_i(t-1)
        s_wgt[tt][i] = v;
    }
    __syncthreads();
    // ---- partial-sum tables ----
    for (int idx = tid; idx < 11 * 32; idx += NTHREADS) {
        int tt = idx >> 5, l = idx & 31;
        float s = 0.f;
        #pragma unroll
        for (int bit = 0; bit < 5; bit++)
            if ((l >> bit) & 1) s += s_wgt[tt][9 - bit];
        s_lane[idx] = s;
    }
    for (int idx = tid; idx < 11 * 8; idx += NTHREADS) {
        int tt = idx >> 3, r = idx & 7;
        float s = 0.f;
        #pragma unroll
        for (int bit = 0; bit < 3; bit++)
            if ((r >> bit) & 1) s += s_wgt[tt][4 - bit];
        s_reg[idx] = s;
    }
    for (int idx = tid; idx < 11 * 4; idx += NTHREADS) {
        int tt = idx >> 2, ww = idx & 3;
        float tot = 0.f;
        #pragma unroll
        for (int i = 0; i < NQ; i++) tot += s_wgt[tt][i];
        float s = -0.5f * tot;
        if (ww & 1) s += s_wgt[tt][1];   // w bit0 = j bit8 = qubit 1
        if (ww & 2) s += s_wgt[tt][0];   // w bit1 = j bit9 = qubit 0
        s_w[idx] = s;
    }
    for (int idx = tid; idx < 11 * 11; idx += NTHREADS) {
        int tt = idx / 11, k = idx - tt * 11;
        float v = 0.f;
        if (tt > 0) {
            const float inv = 0.15811388300841897f;  // 1/(2*sqrt(10))
            float theta = gs[b * TSTEPS + tt - 1] * inv;
            float zs = 10.f - 2.f * (float)k;
            float ps = 0.5f * (zs * zs - 10.f);
            v = -0.5f * theta * ps;
        }
        s_phi[idx] = v;
    }

    // ---- load amplitudes + norm ----
    u64 psi[AMPS];
    float nrm = 0.f;
    #pragma unroll
    for (int r = 0; r < AMPS; r++) {
        int j = (w << 8) | (r << 5) | lane;
        float re = in_re[b * DIM + j];
        float im = in_im[b * DIM + j];
        psi[r] = pk(re, im);
        nrm += re * re + im * im;
    }
    #pragma unroll
    for (int off = 16; off; off >>= 1)
        nrm += __shfl_xor_sync(0xFFFFFFFFu, nrm, off);
    if (lane == 0) s_nrm[w] = nrm;
    __syncthreads();
    const float invn = rsqrtf(s_nrm[0] + s_nrm[1] + s_nrm[2] + s_nrm[3]);
    const int k0 = __popc(lane) + __popc(w);

    // ---- E_t diagonal then 10 real rotations, t = 0..9; E_10 at the end ----
    #pragma unroll 1
    for (int tt = 0; tt < TSTEPS; tt++) {
        // diagonal E_tt
        {
            float base = s_lane[tt * 32 + lane] + s_w[tt * 4 + w];
            #pragma unroll
            for (int r = 0; r < AMPS; r++) {
                float ph = base + s_reg[tt * 8 + r] + s_phi[tt * 11 + k0 + __popc(r)];
                float sn, cn; __sincosf(ph, &sn, &cn);
                psi[r] = ffma2(pk(-sn, sn), swp(psi[r]), fmul2(pk(cn, cn), psi[r]));
            }
        }
        // qubits 0,1: cross-warp exchange (double buffer, 1 barrier each)
        #pragma unroll
        for (int q = 0; q < 2; q++) {
            const int mw = 2 >> q;
            float2 cs = s_rot[tt * NQ + q];
            #pragma unroll
            for (int r = 0; r < AMPS; r++)
                s_x[q][(w << 8) | (r << 5) | lane] = psi[r];
            __syncthreads();
            float so = (w & mw) ? cs.y : -cs.y;
            u64 C2 = pk(cs.x, cs.x), S2 = pk(so, so);
            const int pbase = ((w ^ mw) << 8) | lane;
            #pragma unroll
            for (int r = 0; r < AMPS; r++)
                psi[r] = ffma2(S2, s_x[q][pbase | (r << 5)], fmul2(C2, psi[r]));
        }
        // qubits 2..4: register-local real butterflies
        #pragma unroll
        for (int i = 2; i < 5; i++) {
            const int m = 1 << (4 - i);
            float2 cs = s_rot[tt * NQ + i];
            u64 C2 = pk(cs.x, cs.x), S2 = pk(cs.y, cs.y), Sn = pk(-cs.y, -cs.y);
            #pragma unroll
            for (int rr = 0; rr < AMPS / 2; rr++) {
                int r0 = ((rr & ~(m - 1)) << 1) | (rr & (m - 1));
                int r1 = r0 | m;
                u64 p0 = psi[r0], p1 = psi[r1];
                psi[r0] = ffma2(Sn, p1, fmul2(C2, p0));
                psi[r1] = ffma2(S2, p0, fmul2(C2, p1));
            }
        }
        // qubits 5..9: lane-bit real rotations via shuffle
        #pragma unroll
        for (int i = 5; i < 10; i++) {
            const int m = 1 << (9 - i);
            float2 cs = s_rot[tt * NQ + i];
            float so = (lane & m) ? cs.y : -cs.y;
            u64 C2 = pk(cs.x, cs.x), S2 = pk(so, so);
            #pragma unroll
            for (int r = 0; r < AMPS; r++) {
                float x, y; upk(psi[r], x, y);
                float ox = __shfl_xor_sync(0xFFFFFFFFu, x, m);
                float oy = __shfl_xor_sync(0xFFFFFFFFu, y, m);
                psi[r] = ffma2(S2, pk(ox, oy), fmul2(C2, psi[r]));
            }
        }
    }

    // ---- final diagonal E_10, then store with deferred normalization ----
    {
        float base = s_lane[10 * 32 + lane] + s_w[10 * 4 + w];
        #pragma unroll
        for (int r = 0; r < AMPS; r++) {
            float ph = base + s_reg[10 * 8 + r] + s_phi[10 * 11 + k0 + __popc(r)];
            float sn, cn; __sincosf(ph, &sn, &cn);
            psi[r] = ffma2(pk(-sn, sn), swp(psi[r]), fmul2(pk(cn, cn), psi[r]));
        }
    }
    #pragma unroll
    for (int r = 0; r < AMPS; r++) {
        int j = (w << 8) | (r << 5) | lane;
        float x, y; upk(psi[r], x, y);
        out[b * DIM + j]               = x * invn;
        out[NDATA * DIM + b * DIM + j] = y * invn;
    }
}

extern "C" void kernel_launch(void* const* d_in, const int* in_sizes, int n_in,
                              void* d_out, int out_size)
{
    const float* in_re = (const float*)d_in[0];
    const float* in_im = (const float*)d_in[1];
    const float* phis  = (const float*)d_in[2];
    const float* gs    = (const float*)d_in[3];
    float* out = (float*)d_out;
    scramble_kernel<<<NDATA, NTHREADS>>>(in_re, in_im, phis, gs, out);
}